// round 11
// baseline (speedup 1.0000x reference)
#include <cuda_runtime.h>
#include <cuda_fp16.h>
#include <cstdint>

#define MAXN 50000
#define MAXE 1600000
#define F_IN 512
#define C1 64      // heads*hid = 8*8
#define HEADS 8
#define CLS 16
#define SCAN_B 256

// packed fp32x2 FMA (sm_103a)
#define FMA_F32X2(d, a, b, c) \
    asm("fma.rn.f32x2 %0, %1, %2, %3;" : "=l"(d) : "l"(a), "l"(b), "l"(c))
#define PACK_DUP_F32X2(d, f) \
    asm("mov.b64 %0, {%1, %1};" : "=l"(d) : "r"(__float_as_uint(f)))

// ---------------- scratch ----------------
__device__ __align__(16) int   g_deg[MAXN];        // zeroed via cudaMemsetAsync
__device__ __align__(16) int   g_tmp[MAXN];        // zeroed inside k_scan1
__device__ __align__(16) int   g_rowptr[MAXN + 1]; // block-local exclusive prefix
__device__ __align__(16) int   g_bsum[256];
__device__ __align__(16) int   g_boff[256];        // per-block offset
__device__            int      g_arrive = 0;       // last-block ticket (returns to 0 each call)
__device__ __align__(16) int   g_col[MAXE + MAXN];
__device__ __align__(16) float g_h1[(size_t)MAXN * C1];
__device__ __align__(16) float g_asrc1[MAXN * HEADS];
__device__ __align__(16) float g_adst1[MAXN * HEADS];
__device__ __align__(16) float g_h1act[(size_t)MAXN * C1];
__device__ __align__(16) float g_h2[(size_t)MAXN * CLS];
__device__ __align__(16) float g_asrc2[MAXN];
__device__ __align__(16) float g_adst2[MAXN];

// global rowptr = block-local prefix + per-block offset
__device__ __forceinline__ int rowp(int i) {
    return g_rowptr[i] + g_boff[i >> 8];
}

// Per-block int64-vs-int32 probe: deterministic for fixed input.
__device__ __forceinline__ bool block_detect_is64(const int* w32, long long e0, int E) {
    int hi = 0;
    long long e = e0 + threadIdx.x;
    if (e < E) hi = w32[2 * e + 1];
    return !__syncthreads_or(hi != 0);
}

__device__ __forceinline__ int load_edge(const void* ei, bool is64, size_t pos) {
    return is64 ? (int)((const long long*)ei)[pos] : ((const int*)ei)[pos];
}

// ================= fused GEMM1 (f32x2 packed) + edge count =================
#define TK 32
__global__ __launch_bounds__(256) void k_gemm1_count(
    const float* __restrict__ x, const float* __restrict__ W,
    const float* __restrict__ attS, const float* __restrict__ attD,
    const void* __restrict__ ei, int n, int E, int GB)
{
    if (blockIdx.x >= GB) {
        long long e0 = (long long)(blockIdx.x - GB) * 256;
        bool is64 = block_detect_is64((const int*)ei, e0, E);
        long long e = e0 + threadIdx.x;
        if (e < E) {
            int d = load_edge(ei, is64, (size_t)E + e);
            if ((unsigned)d < (unsigned)n) atomicAdd(&g_deg[d], 1);
        }
        return;
    }

    __shared__ __align__(16) float xs[TK][256 + 4];
    __shared__ __align__(16) float ws[TK][64 + 4];
    int tid = threadIdx.x;
    int tx = tid & 7;       // col group (== head)
    int ty = tid >> 3;      // row group 0..31
    int r0 = blockIdx.x * 256;

    unsigned long long acc2[8][4];
#pragma unroll
    for (int r = 0; r < 8; r++)
#pragma unroll
        for (int c = 0; c < 4; c++) acc2[r][c] = 0ull;

    for (int kc = 0; kc < F_IN; kc += TK) {
#pragma unroll
        for (int i = 0; i < 8; i++) {
            int idx = tid + 256 * i;
            int row = idx >> 3;
            int k4  = idx & 7;
            float4 v = make_float4(0.f, 0.f, 0.f, 0.f);
            int gr = r0 + row;
            if (gr < n) v = *(const float4*)&x[(size_t)gr * F_IN + kc + k4 * 4];
            xs[k4 * 4 + 0][row] = v.x;
            xs[k4 * 4 + 1][row] = v.y;
            xs[k4 * 4 + 2][row] = v.z;
            xs[k4 * 4 + 3][row] = v.w;
        }
#pragma unroll
        for (int i = 0; i < 2; i++) {
            int idx = tid + 256 * i;
            int k  = idx >> 4;
            int c4 = idx & 15;
            float4 v = *(const float4*)&W[(size_t)(kc + k) * C1 + c4 * 4];
            ws[k][c4 * 4 + 0] = v.x;
            ws[k][c4 * 4 + 1] = v.y;
            ws[k][c4 * 4 + 2] = v.z;
            ws[k][c4 * 4 + 3] = v.w;
        }
        __syncthreads();
#pragma unroll
        for (int k = 0; k < TK; k++) {
            float4 xa = *(const float4*)&xs[k][ty * 8];
            float4 xb = *(const float4*)&xs[k][ty * 8 + 4];
            unsigned long long wv2[4];
            {
                const ulonglong2* wp = (const ulonglong2*)&ws[k][tx * 8];
                ulonglong2 w01 = wp[0];
                ulonglong2 w23 = wp[1];
                wv2[0] = w01.x; wv2[1] = w01.y;
                wv2[2] = w23.x; wv2[3] = w23.y;
            }
            unsigned long long xp[8];
            PACK_DUP_F32X2(xp[0], xa.x); PACK_DUP_F32X2(xp[1], xa.y);
            PACK_DUP_F32X2(xp[2], xa.z); PACK_DUP_F32X2(xp[3], xa.w);
            PACK_DUP_F32X2(xp[4], xb.x); PACK_DUP_F32X2(xp[5], xb.y);
            PACK_DUP_F32X2(xp[6], xb.z); PACK_DUP_F32X2(xp[7], xb.w);
#pragma unroll
            for (int r = 0; r < 8; r++)
#pragma unroll
                for (int c = 0; c < 4; c++)
                    FMA_F32X2(acc2[r][c], xp[r], wv2[c], acc2[r][c]);
        }
        __syncthreads();
    }

    float as[8], ad[8];
#pragma unroll
    for (int c = 0; c < 8; c++) { as[c] = attS[tx * 8 + c]; ad[c] = attD[tx * 8 + c]; }
#pragma unroll
    for (int r = 0; r < 8; r++) {
        int gr = r0 + ty * 8 + r;
        if (gr < n) {
            float a[8];
#pragma unroll
            for (int c = 0; c < 4; c++) {
                uint2 u = *(uint2*)&acc2[r][c];
                a[2 * c]     = __uint_as_float(u.x);
                a[2 * c + 1] = __uint_as_float(u.y);
            }
            float s = 0.f, d = 0.f;
#pragma unroll
            for (int c = 0; c < 8; c++) {
                s = fmaf(a[c], as[c], s);
                d = fmaf(a[c], ad[c], d);
            }
            float4 v0 = make_float4(a[0], a[1], a[2], a[3]);
            float4 v1 = make_float4(a[4], a[5], a[6], a[7]);
            *(float4*)&g_h1[(size_t)gr * C1 + tx * 8]     = v0;
            *(float4*)&g_h1[(size_t)gr * C1 + tx * 8 + 4] = v1;
            g_asrc1[gr * HEADS + tx] = s;
            g_adst1[gr * HEADS + tx] = d;
        }
    }
}

// ================= single-pass block scan (last block folds scan2) =================
__device__ __forceinline__ int warp_incl_scan(int x) {
#pragma unroll
    for (int o = 1; o < 32; o <<= 1) {
        int t = __shfl_up_sync(0xffffffffu, x, o);
        if ((threadIdx.x & 31) >= o) x += t;
    }
    return x;
}

__global__ void k_scan1(int n, int nb) {
    __shared__ int wsum[8];
    __shared__ int is_last;
    int i = blockIdx.x * SCAN_B + threadIdx.x;
    int lane = threadIdx.x & 31, wid = threadIdx.x >> 5;
    if (i < n) g_tmp[i] = 0;                // replaces the g_tmp memset
    int v = (i < n) ? g_deg[i] + 1 : 0;     // +1 = self-loop
    int x = warp_incl_scan(v);
    if (lane == 31) wsum[wid] = x;
    __syncthreads();
    if (wid == 0) {
        int y = (lane < 8) ? wsum[lane] : 0;
#pragma unroll
        for (int o = 1; o < 8; o <<= 1) {
            int t = __shfl_up_sync(0xffffffffu, y, o);
            if (lane >= o) y += t;
        }
        if (lane < 8) wsum[lane] = y;
    }
    __syncthreads();
    int excl = x - v + (wid > 0 ? wsum[wid - 1] : 0);
    if (i <= n) g_rowptr[i] = excl;
    if (threadIdx.x == 0) g_bsum[blockIdx.x] = wsum[7];

    // last arriving block computes g_boff (folds old k_scan2)
    __threadfence();
    if (threadIdx.x == 0) {
        int t = atomicAdd(&g_arrive, 1);
        is_last = (t == gridDim.x - 1);
    }
    __syncthreads();
    if (is_last) {
        int tt = threadIdx.x;
        int vv = (tt < nb) ? g_bsum[tt] : 0;
        int xx = warp_incl_scan(vv);
        if (lane == 31) wsum[wid] = xx;
        __syncthreads();
        if (wid == 0) {
            int y = (lane < 8) ? wsum[lane] : 0;
#pragma unroll
            for (int o = 1; o < 8; o <<= 1) {
                int t2 = __shfl_up_sync(0xffffffffu, y, o);
                if (lane >= o) y += t2;
            }
            if (lane < 8) wsum[lane] = y;
        }
        __syncthreads();
        int ex2 = xx - vv + (wid > 0 ? wsum[wid - 1] : 0);
        if (tt < nb) g_boff[tt] = ex2;
        if (tt == 0) g_arrive = 0;          // reset for next graph replay
    }
}

// ================= scatter (edges then self-loops) =================
__global__ void k_scatter(const void* __restrict__ ei, int E, int n) {
    long long e0 = (long long)blockIdx.x * 256;
    bool is64 = block_detect_is64((const int*)ei, e0, E);
    long long i = e0 + threadIdx.x;
    int s, d;
    if (i < E) {
        d = load_edge(ei, is64, (size_t)E + i);
        if ((unsigned)d >= (unsigned)n) return;       // must match count guard
        s = load_edge(ei, is64, (size_t)i);
        if ((unsigned)s >= (unsigned)n) s = 0;
    } else if (i < E + n) {
        s = d = (int)(i - E);
    } else return;
    int pos = rowp(d) + atomicAdd(&g_tmp[d], 1);
    g_col[pos] = s;
}

// ================= layer-1 edge softmax + aggregate + bias + elu =================
// one warp per dst node; lane owns channels 2l, 2l+1 (head hown = l>>2); 4-way unroll.
__global__ __launch_bounds__(256) void agg1(const float* __restrict__ bias1, int n) {
    int warp = (blockIdx.x * blockDim.x + threadIdx.x) >> 5;
    int lane = threadIdx.x & 31;
    if (warp >= n) return;
    int nd = warp;
    int h    = lane & 7;
    int hown = lane >> 2;
    float laneden = (lane < 8) ? 1.f : 0.f;

    float adv = g_adst1[nd * HEADS + h];
    int beg = rowp(nd), end = rowp(nd + 1);
    float accx = 0.f, accy = 0.f, den = 0.f;

    int e = beg;
    for (; e + 4 <= end; e += 4) {
        int s0 = g_col[e];
        int s1 = g_col[e + 1];
        int s2 = g_col[e + 2];
        int s3 = g_col[e + 3];
        float a0 = g_asrc1[s0 * HEADS + h] + adv;
        float a1 = g_asrc1[s1 * HEADS + h] + adv;
        float a2 = g_asrc1[s2 * HEADS + h] + adv;
        float a3 = g_asrc1[s3 * HEADS + h] + adv;
        float2 f0 = *(const float2*)&g_h1[(size_t)s0 * C1 + 2 * lane];
        float2 f1 = *(const float2*)&g_h1[(size_t)s1 * C1 + 2 * lane];
        float2 f2 = *(const float2*)&g_h1[(size_t)s2 * C1 + 2 * lane];
        float2 f3 = *(const float2*)&g_h1[(size_t)s3 * C1 + 2 * lane];
        a0 = a0 > 0.f ? a0 : 0.2f * a0;
        a1 = a1 > 0.f ? a1 : 0.2f * a1;
        a2 = a2 > 0.f ? a2 : 0.2f * a2;
        a3 = a3 > 0.f ? a3 : 0.2f * a3;
        float w0 = __expf(a0);
        float w1 = __expf(a1);
        float w2 = __expf(a2);
        float w3 = __expf(a3);
        den = fmaf((w0 + w1) + (w2 + w3), laneden, den);
        float w0o = __shfl_sync(0xffffffffu, w0, hown);
        float w1o = __shfl_sync(0xffffffffu, w1, hown);
        float w2o = __shfl_sync(0xffffffffu, w2, hown);
        float w3o = __shfl_sync(0xffffffffu, w3, hown);
        accx = fmaf(w0o, f0.x, accx);
        accy = fmaf(w0o, f0.y, accy);
        accx = fmaf(w1o, f1.x, accx);
        accy = fmaf(w1o, f1.y, accy);
        accx = fmaf(w2o, f2.x, accx);
        accy = fmaf(w2o, f2.y, accy);
        accx = fmaf(w3o, f3.x, accx);
        accy = fmaf(w3o, f3.y, accy);
    }
    for (; e < end; e++) {
        int s0 = g_col[e];
        float a0 = g_asrc1[s0 * HEADS + h] + adv;
        float2 f0 = *(const float2*)&g_h1[(size_t)s0 * C1 + 2 * lane];
        a0 = a0 > 0.f ? a0 : 0.2f * a0;
        float w0 = __expf(a0);
        den = fmaf(w0, laneden, den);
        float w0o = __shfl_sync(0xffffffffu, w0, hown);
        accx = fmaf(w0o, f0.x, accx);
        accy = fmaf(w0o, f0.y, accy);
    }
    float deno = __shfl_sync(0xffffffffu, den, hown);
    float2 bv = *(const float2*)&bias1[2 * lane];
    float ox = accx / deno + bv.x;
    float oy = accy / deno + bv.y;
    ox = ox > 0.f ? ox : expm1f(ox);          // elu
    oy = oy > 0.f ? oy : expm1f(oy);
    *(float2*)&g_h1act[(size_t)nd * C1 + 2 * lane] = make_float2(ox, oy);
}

// ================= GEMM2: h2 = h1act @ W2, fused scalar logits =================
__global__ __launch_bounds__(256) void gemm2(
    const float* __restrict__ W2, const float* __restrict__ aS,
    const float* __restrict__ aD, int n)
{
    __shared__ float ws[64 * 16];
    int tid = threadIdx.x;
    for (int i = tid; i < 64 * 16; i += 256) ws[i] = W2[i];
    __syncthreads();

    int warp = tid >> 5, lane = tid & 31;
    int row0 = (blockIdx.x * 8 + warp) * 2 + (lane >> 4);
    int c = lane & 15;
    bool ok = row0 < n;
    int row = ok ? row0 : 0;

    float xr[4];
#pragma unroll
    for (int j = 0; j < 4; j++) xr[j] = g_h1act[(size_t)row * C1 + c + 16 * j];

    float acc = 0.f;
#pragma unroll
    for (int k = 0; k < 64; k++) {
        float xk = __shfl_sync(0xffffffffu, xr[k >> 4], (lane & 16) | (k & 15));
        acc = fmaf(xk, ws[k * 16 + c], acc);
    }

    float ts = acc * aS[c];
    float td = acc * aD[c];
#pragma unroll
    for (int off = 8; off >= 1; off >>= 1) {
        ts += __shfl_xor_sync(0xffffffffu, ts, off);
        td += __shfl_xor_sync(0xffffffffu, td, off);
    }
    if (ok) {
        g_h2[(size_t)row * CLS + c] = acc;
        if (c == 0) { g_asrc2[row] = ts; g_adst2[row] = td; }
    }
}

// ================= layer-2 aggregate + bias + log_softmax =================
__global__ __launch_bounds__(256) void agg2(
    const float* __restrict__ bias2, float* __restrict__ out, int n)
{
    int warp = (blockIdx.x * blockDim.x + threadIdx.x) >> 5;
    int lane = threadIdx.x & 31;
    int node0 = warp * 2 + (lane >> 4);
    int c = lane & 15;
    bool ok = node0 < n;
    int nd = ok ? node0 : 0;

    float adv = g_adst2[nd];
    int beg = rowp(nd);
    int end = ok ? rowp(nd + 1) : beg;
    float acc = 0.f, den = 0.f;
    int e = beg;
    for (; e + 2 <= end; e += 2) {
        int s0 = g_col[e], s1 = g_col[e + 1];
        float a0 = g_asrc2[s0] + adv;
        float a1 = g_asrc2[s1] + adv;
        float f0 = g_h2[(size_t)s0 * CLS + c];
        float f1 = g_h2[(size_t)s1 * CLS + c];
        a0 = a0 > 0.f ? a0 : 0.2f * a0;
        a1 = a1 > 0.f ? a1 : 0.2f * a1;
        float w0 = __expf(a0), w1 = __expf(a1);
        den += w0 + w1;
        acc = fmaf(w0, f0, acc);
        acc = fmaf(w1, f1, acc);
    }
    if (e < end) {
        int s0 = g_col[e];
        float a0 = g_asrc2[s0] + adv;
        a0 = a0 > 0.f ? a0 : 0.2f * a0;
        float w0 = __expf(a0);
        den += w0;
        acc = fmaf(w0, g_h2[(size_t)s0 * CLS + c], acc);
    }
    float val = ok ? (acc / den + bias2[c]) : 0.f;
    float m = val;
#pragma unroll
    for (int off = 8; off >= 1; off >>= 1)
        m = fmaxf(m, __shfl_xor_sync(0xffffffffu, m, off));
    float ex = __expf(val - m);
    float s = ex;
#pragma unroll
    for (int off = 8; off >= 1; off >>= 1)
        s += __shfl_xor_sync(0xffffffffu, s, off);
    if (ok) out[(size_t)node0 * CLS + c] = val - m - __logf(s);
}

// ---------------- launch ----------------
extern "C" void kernel_launch(void* const* d_in, const int* in_sizes, int n_in,
                              void* d_out, int out_size) {
    const float* x     = (const float*)d_in[0];
    const void*  ei    = d_in[1];
    const float* W1    = (const float*)d_in[2];
    const float* attS1 = (const float*)d_in[3];
    const float* attD1 = (const float*)d_in[4];
    const float* bias1 = (const float*)d_in[5];
    const float* W2    = (const float*)d_in[6];
    const float* attS2 = (const float*)d_in[7];
    const float* attD2 = (const float*)d_in[8];
    const float* bias2 = (const float*)d_in[9];
    float* out = (float*)d_out;

    int n = in_sizes[0] / F_IN;      // 50000
    int E = in_sizes[1] / 2;         // 1600000

    void* p_deg = nullptr;
    cudaGetSymbolAddress(&p_deg, g_deg);
    cudaMemsetAsync(p_deg, 0, (size_t)n * sizeof(int));

    int GB = (n + 255) / 256;                 // gemm1 blocks (196)
    int CB = (E + 255) / 256;                 // count blocks (6250)
    int nb = (n + SCAN_B - 1) / SCAN_B;       // scan blocks (196)

    k_gemm1_count<<<GB + CB, 256>>>(x, W1, attS1, attD1, ei, n, E, GB); // kernel 1
    k_scan1<<<nb, SCAN_B>>>(n, nb);                                     // kernel 2 (scan2 folded in)
    k_scatter<<<(E + n + 255) / 256, 256>>>(ei, E, n);                  // kernel 3
    agg1 <<<(n + 7) / 8, 256>>>(bias1, n);                              // kernel 4 <- ncu lands here
    gemm2<<<(n + 15) / 16, 256>>>(W2, attS2, attD2, n);
    agg2 <<<(n + 15) / 16, 256>>>(bias2, out, n);
}

// round 12
// speedup vs baseline: 1.0350x; 1.0350x over previous
#include <cuda_runtime.h>
#include <cuda_fp16.h>
#include <cstdint>

#define MAXN 50000
#define MAXE 1600000
#define F_IN 512
#define C1 64      // heads*hid = 8*8
#define HEADS 8
#define CLS 16
#define SCAN_B 256

// packed fp32x2 FMA (sm_103a)
#define FMA_F32X2(d, a, b, c) \
    asm("fma.rn.f32x2 %0, %1, %2, %3;" : "=l"(d) : "l"(a), "l"(b), "l"(c))
#define PACK_DUP_F32X2(d, f) \
    asm("mov.b64 %0, {%1, %1};" : "=l"(d) : "r"(__float_as_uint(f)))

// ---------------- scratch ----------------
__device__ __align__(16) int   g_deg[MAXN];        // zeroed via cudaMemsetAsync
__device__ __align__(16) int   g_tmp[MAXN];        // zeroed inside k_scan1
__device__ __align__(16) int   g_rowptr[MAXN + 1]; // block-local exclusive prefix
__device__ __align__(16) int   g_bsum[256];
__device__ __align__(16) int   g_boff[256];        // per-block offset
__device__            int      g_arrive = 0;       // last-block ticket (returns to 0 each call)
__device__ __align__(16) int   g_col[MAXE + MAXN];
__device__ __align__(16) float g_h1[(size_t)MAXN * C1];
__device__ __align__(16) float g_asrc1[MAXN * HEADS];
__device__ __align__(16) float g_adst1[MAXN * HEADS];
__device__ __align__(16) float g_h1act[(size_t)MAXN * C1];
__device__ __align__(16) float g_h2[(size_t)MAXN * CLS];
__device__ __align__(16) float g_asrc2[MAXN];
__device__ __align__(16) float g_adst2[MAXN];

// global rowptr = block-local prefix + per-block offset
__device__ __forceinline__ int rowp(int i) {
    return g_rowptr[i] + g_boff[i >> 8];
}

// Per-block int64-vs-int32 probe: deterministic for fixed input.
__device__ __forceinline__ bool block_detect_is64(const int* w32, long long e0, int E) {
    int hi = 0;
    long long e = e0 + threadIdx.x;
    if (e < E) hi = w32[2 * e + 1];
    return !__syncthreads_or(hi != 0);
}

__device__ __forceinline__ int load_edge(const void* ei, bool is64, size_t pos) {
    return is64 ? (int)((const long long*)ei)[pos] : ((const int*)ei)[pos];
}

// ================= fused GEMM1 (f32x2 packed) + edge count =================
#define TK 32
__global__ __launch_bounds__(256) void k_gemm1_count(
    const float* __restrict__ x, const float* __restrict__ W,
    const float* __restrict__ attS, const float* __restrict__ attD,
    const void* __restrict__ ei, int n, int E, int GB)
{
    if (blockIdx.x >= GB) {
        long long e0 = (long long)(blockIdx.x - GB) * 256;
        bool is64 = block_detect_is64((const int*)ei, e0, E);
        long long e = e0 + threadIdx.x;
        if (e < E) {
            int d = load_edge(ei, is64, (size_t)E + e);
            if ((unsigned)d < (unsigned)n) atomicAdd(&g_deg[d], 1);
        }
        return;
    }

    __shared__ __align__(16) float xs[TK][256 + 4];
    __shared__ __align__(16) float ws[TK][64 + 4];
    int tid = threadIdx.x;
    int tx = tid & 7;       // col group (== head)
    int ty = tid >> 3;      // row group 0..31
    int r0 = blockIdx.x * 256;

    unsigned long long acc2[8][4];
#pragma unroll
    for (int r = 0; r < 8; r++)
#pragma unroll
        for (int c = 0; c < 4; c++) acc2[r][c] = 0ull;

    for (int kc = 0; kc < F_IN; kc += TK) {
#pragma unroll
        for (int i = 0; i < 8; i++) {
            int idx = tid + 256 * i;
            int row = idx >> 3;
            int k4  = idx & 7;
            float4 v = make_float4(0.f, 0.f, 0.f, 0.f);
            int gr = r0 + row;
            if (gr < n) v = *(const float4*)&x[(size_t)gr * F_IN + kc + k4 * 4];
            xs[k4 * 4 + 0][row] = v.x;
            xs[k4 * 4 + 1][row] = v.y;
            xs[k4 * 4 + 2][row] = v.z;
            xs[k4 * 4 + 3][row] = v.w;
        }
#pragma unroll
        for (int i = 0; i < 2; i++) {
            int idx = tid + 256 * i;
            int k  = idx >> 4;
            int c4 = idx & 15;
            float4 v = *(const float4*)&W[(size_t)(kc + k) * C1 + c4 * 4];
            ws[k][c4 * 4 + 0] = v.x;
            ws[k][c4 * 4 + 1] = v.y;
            ws[k][c4 * 4 + 2] = v.z;
            ws[k][c4 * 4 + 3] = v.w;
        }
        __syncthreads();
#pragma unroll
        for (int k = 0; k < TK; k++) {
            float4 xa = *(const float4*)&xs[k][ty * 8];
            float4 xb = *(const float4*)&xs[k][ty * 8 + 4];
            unsigned long long wv2[4];
            {
                const ulonglong2* wp = (const ulonglong2*)&ws[k][tx * 8];
                ulonglong2 w01 = wp[0];
                ulonglong2 w23 = wp[1];
                wv2[0] = w01.x; wv2[1] = w01.y;
                wv2[2] = w23.x; wv2[3] = w23.y;
            }
            unsigned long long xp[8];
            PACK_DUP_F32X2(xp[0], xa.x); PACK_DUP_F32X2(xp[1], xa.y);
            PACK_DUP_F32X2(xp[2], xa.z); PACK_DUP_F32X2(xp[3], xa.w);
            PACK_DUP_F32X2(xp[4], xb.x); PACK_DUP_F32X2(xp[5], xb.y);
            PACK_DUP_F32X2(xp[6], xb.z); PACK_DUP_F32X2(xp[7], xb.w);
#pragma unroll
            for (int r = 0; r < 8; r++)
#pragma unroll
                for (int c = 0; c < 4; c++)
                    FMA_F32X2(acc2[r][c], xp[r], wv2[c], acc2[r][c]);
        }
        __syncthreads();
    }

    float as[8], ad[8];
#pragma unroll
    for (int c = 0; c < 8; c++) { as[c] = attS[tx * 8 + c]; ad[c] = attD[tx * 8 + c]; }
#pragma unroll
    for (int r = 0; r < 8; r++) {
        int gr = r0 + ty * 8 + r;
        if (gr < n) {
            float a[8];
#pragma unroll
            for (int c = 0; c < 4; c++) {
                uint2 u = *(uint2*)&acc2[r][c];
                a[2 * c]     = __uint_as_float(u.x);
                a[2 * c + 1] = __uint_as_float(u.y);
            }
            float s = 0.f, d = 0.f;
#pragma unroll
            for (int c = 0; c < 8; c++) {
                s = fmaf(a[c], as[c], s);
                d = fmaf(a[c], ad[c], d);
            }
            float4 v0 = make_float4(a[0], a[1], a[2], a[3]);
            float4 v1 = make_float4(a[4], a[5], a[6], a[7]);
            *(float4*)&g_h1[(size_t)gr * C1 + tx * 8]     = v0;
            *(float4*)&g_h1[(size_t)gr * C1 + tx * 8 + 4] = v1;
            g_asrc1[gr * HEADS + tx] = s;
            g_adst1[gr * HEADS + tx] = d;
        }
    }
}

// ================= single-pass block scan (last block folds scan2) =================
__device__ __forceinline__ int warp_incl_scan(int x) {
#pragma unroll
    for (int o = 1; o < 32; o <<= 1) {
        int t = __shfl_up_sync(0xffffffffu, x, o);
        if ((threadIdx.x & 31) >= o) x += t;
    }
    return x;
}

__global__ void k_scan1(int n, int nb) {
    __shared__ int wsum[8];
    __shared__ int is_last;
    int i = blockIdx.x * SCAN_B + threadIdx.x;
    int lane = threadIdx.x & 31, wid = threadIdx.x >> 5;
    if (i < n) g_tmp[i] = 0;                // replaces the g_tmp memset
    int v = (i < n) ? g_deg[i] + 1 : 0;     // +1 = self-loop
    int x = warp_incl_scan(v);
    if (lane == 31) wsum[wid] = x;
    __syncthreads();
    if (wid == 0) {
        int y = (lane < 8) ? wsum[lane] : 0;
#pragma unroll
        for (int o = 1; o < 8; o <<= 1) {
            int t = __shfl_up_sync(0xffffffffu, y, o);
            if (lane >= o) y += t;
        }
        if (lane < 8) wsum[lane] = y;
    }
    __syncthreads();
    int excl = x - v + (wid > 0 ? wsum[wid - 1] : 0);
    if (i <= n) g_rowptr[i] = excl;
    if (threadIdx.x == 0) g_bsum[blockIdx.x] = wsum[7];

    // last arriving block computes g_boff (folds old k_scan2)
    __threadfence();
    if (threadIdx.x == 0) {
        int t = atomicAdd(&g_arrive, 1);
        is_last = (t == gridDim.x - 1);
    }
    __syncthreads();
    if (is_last) {
        int tt = threadIdx.x;
        int vv = (tt < nb) ? g_bsum[tt] : 0;
        int xx = warp_incl_scan(vv);
        if (lane == 31) wsum[wid] = xx;
        __syncthreads();
        if (wid == 0) {
            int y = (lane < 8) ? wsum[lane] : 0;
#pragma unroll
            for (int o = 1; o < 8; o <<= 1) {
                int t2 = __shfl_up_sync(0xffffffffu, y, o);
                if (lane >= o) y += t2;
            }
            if (lane < 8) wsum[lane] = y;
        }
        __syncthreads();
        int ex2 = xx - vv + (wid > 0 ? wsum[wid - 1] : 0);
        if (tt < nb) g_boff[tt] = ex2;
        if (tt == 0) g_arrive = 0;          // reset for next graph replay
    }
}

// ================= scatter (edges then self-loops) =================
__global__ void k_scatter(const void* __restrict__ ei, int E, int n) {
    long long e0 = (long long)blockIdx.x * 256;
    bool is64 = block_detect_is64((const int*)ei, e0, E);
    long long i = e0 + threadIdx.x;
    int s, d;
    if (i < E) {
        d = load_edge(ei, is64, (size_t)E + i);
        if ((unsigned)d >= (unsigned)n) return;       // must match count guard
        s = load_edge(ei, is64, (size_t)i);
        if ((unsigned)s >= (unsigned)n) s = 0;
    } else if (i < E + n) {
        s = d = (int)(i - E);
    } else return;
    int pos = rowp(d) + atomicAdd(&g_tmp[d], 1);
    g_col[pos] = s;
}

// ================= layer-1 edge softmax + aggregate + bias + elu =================
// one warp per dst node. Lane decomposition:
//   exp work:   (j = lane>>3, h = lane&7) -> lane computes leaky+exp for edge-slot j, head h
//   aggregation: lane owns channels 2l, 2l+1 (head hown = lane>>2)
// Main loop: 1 int4 col load + 1 asrc load + 1 exp + 4 feature LDG.64 + 4 SHFL per 4 edges.
__global__ __launch_bounds__(256) void agg1(const float* __restrict__ bias1, int n) {
    int warp = (blockIdx.x * blockDim.x + threadIdx.x) >> 5;
    int lane = threadIdx.x & 31;
    if (warp >= n) return;
    int nd = warp;
    int h    = lane & 7;      // head this lane exponentiates
    int j    = lane >> 3;     // edge slot (0..3) this lane exponentiates
    int hown = lane >> 2;     // head owning channels 2l, 2l+1
    float jden = (lane < 8) ? 1.f : 0.f;   // scalar-path den gate (j==0 lanes)

    float adv = g_adst1[nd * HEADS + h];
    int beg = rowp(nd), end = rowp(nd + 1);
    float accx = 0.f, accy = 0.f, den = 0.f;

    int e = beg;
    // prologue: advance to 4-aligned element index (g_col base is 16B aligned)
    for (; e < end && (e & 3); e++) {
        int s0 = g_col[e];
        float a0 = g_asrc1[s0 * HEADS + h] + adv;
        float2 f0 = *(const float2*)&g_h1[(size_t)s0 * C1 + 2 * lane];
        a0 = a0 > 0.f ? a0 : 0.2f * a0;
        float w0 = __expf(a0);
        den = fmaf(w0, jden, den);
        float w0o = __shfl_sync(0xffffffffu, w0, hown);
        accx = fmaf(w0o, f0.x, accx);
        accy = fmaf(w0o, f0.y, accy);
    }
    // main: 4 edges per iteration, vector col load, 1 exp per lane
    for (; e + 4 <= end; e += 4) {
        int4 c4 = *(const int4*)&g_col[e];
        int sj = (j == 0) ? c4.x : (j == 1) ? c4.y : (j == 2) ? c4.z : c4.w;
        float a = g_asrc1[sj * HEADS + h] + adv;
        float2 f0 = *(const float2*)&g_h1[(size_t)c4.x * C1 + 2 * lane];
        float2 f1 = *(const float2*)&g_h1[(size_t)c4.y * C1 + 2 * lane];
        float2 f2 = *(const float2*)&g_h1[(size_t)c4.z * C1 + 2 * lane];
        float2 f3 = *(const float2*)&g_h1[(size_t)c4.w * C1 + 2 * lane];
        a = a > 0.f ? a : 0.2f * a;           // leaky_relu
        float w = __expf(a);
        den += w;                             // (j,h) slot: each edge counted once after fold
        float w0o = __shfl_sync(0xffffffffu, w, hown);
        float w1o = __shfl_sync(0xffffffffu, w, 8 + hown);
        float w2o = __shfl_sync(0xffffffffu, w, 16 + hown);
        float w3o = __shfl_sync(0xffffffffu, w, 24 + hown);
        accx = fmaf(w0o, f0.x, accx);
        accy = fmaf(w0o, f0.y, accy);
        accx = fmaf(w1o, f1.x, accx);
        accy = fmaf(w1o, f1.y, accy);
        accx = fmaf(w2o, f2.x, accx);
        accy = fmaf(w2o, f2.y, accy);
        accx = fmaf(w3o, f3.x, accx);
        accy = fmaf(w3o, f3.y, accy);
    }
    // tail
    for (; e < end; e++) {
        int s0 = g_col[e];
        float a0 = g_asrc1[s0 * HEADS + h] + adv;
        float2 f0 = *(const float2*)&g_h1[(size_t)s0 * C1 + 2 * lane];
        a0 = a0 > 0.f ? a0 : 0.2f * a0;
        float w0 = __expf(a0);
        den = fmaf(w0, jden, den);
        float w0o = __shfl_sync(0xffffffffu, w0, hown);
        accx = fmaf(w0o, f0.x, accx);
        accy = fmaf(w0o, f0.y, accy);
    }
    // fold den over the 4 j-groups (lanes h, h+8, h+16, h+24 share head h)
    den += __shfl_xor_sync(0xffffffffu, den, 8);
    den += __shfl_xor_sync(0xffffffffu, den, 16);
    float deno = __shfl_sync(0xffffffffu, den, hown);   // lane hown holds head hown

    float2 bv = *(const float2*)&bias1[2 * lane];
    float ox = accx / deno + bv.x;
    float oy = accy / deno + bv.y;
    ox = ox > 0.f ? ox : expm1f(ox);          // elu
    oy = oy > 0.f ? oy : expm1f(oy);
    *(float2*)&g_h1act[(size_t)nd * C1 + 2 * lane] = make_float2(ox, oy);
}

// ================= GEMM2: h2 = h1act @ W2, fused scalar logits =================
__global__ __launch_bounds__(256) void gemm2(
    const float* __restrict__ W2, const float* __restrict__ aS,
    const float* __restrict__ aD, int n)
{
    __shared__ float ws[64 * 16];
    int tid = threadIdx.x;
    for (int i = tid; i < 64 * 16; i += 256) ws[i] = W2[i];
    __syncthreads();

    int warp = tid >> 5, lane = tid & 31;
    int row0 = (blockIdx.x * 8 + warp) * 2 + (lane >> 4);
    int c = lane & 15;
    bool ok = row0 < n;
    int row = ok ? row0 : 0;

    float xr[4];
#pragma unroll
    for (int j = 0; j < 4; j++) xr[j] = g_h1act[(size_t)row * C1 + c + 16 * j];

    float acc = 0.f;
#pragma unroll
    for (int k = 0; k < 64; k++) {
        float xk = __shfl_sync(0xffffffffu, xr[k >> 4], (lane & 16) | (k & 15));
        acc = fmaf(xk, ws[k * 16 + c], acc);
    }

    float ts = acc * aS[c];
    float td = acc * aD[c];
#pragma unroll
    for (int off = 8; off >= 1; off >>= 1) {
        ts += __shfl_xor_sync(0xffffffffu, ts, off);
        td += __shfl_xor_sync(0xffffffffu, td, off);
    }
    if (ok) {
        g_h2[(size_t)row * CLS + c] = acc;
        if (c == 0) { g_asrc2[row] = ts; g_adst2[row] = td; }
    }
}

// ================= layer-2 aggregate + bias + log_softmax =================
__global__ __launch_bounds__(256) void agg2(
    const float* __restrict__ bias2, float* __restrict__ out, int n)
{
    int warp = (blockIdx.x * blockDim.x + threadIdx.x) >> 5;
    int lane = threadIdx.x & 31;
    int node0 = warp * 2 + (lane >> 4);
    int c = lane & 15;
    bool ok = node0 < n;
    int nd = ok ? node0 : 0;

    float adv = g_adst2[nd];
    int beg = rowp(nd);
    int end = ok ? rowp(nd + 1) : beg;
    float acc = 0.f, den = 0.f;
    int e = beg;
    for (; e + 2 <= end; e += 2) {
        int s0 = g_col[e], s1 = g_col[e + 1];
        float a0 = g_asrc2[s0] + adv;
        float a1 = g_asrc2[s1] + adv;
        float f0 = g_h2[(size_t)s0 * CLS + c];
        float f1 = g_h2[(size_t)s1 * CLS + c];
        a0 = a0 > 0.f ? a0 : 0.2f * a0;
        a1 = a1 > 0.f ? a1 : 0.2f * a1;
        float w0 = __expf(a0), w1 = __expf(a1);
        den += w0 + w1;
        acc = fmaf(w0, f0, acc);
        acc = fmaf(w1, f1, acc);
    }
    if (e < end) {
        int s0 = g_col[e];
        float a0 = g_asrc2[s0] + adv;
        a0 = a0 > 0.f ? a0 : 0.2f * a0;
        float w0 = __expf(a0);
        den += w0;
        acc = fmaf(w0, g_h2[(size_t)s0 * CLS + c], acc);
    }
    float val = ok ? (acc / den + bias2[c]) : 0.f;
    float m = val;
#pragma unroll
    for (int off = 8; off >= 1; off >>= 1)
        m = fmaxf(m, __shfl_xor_sync(0xffffffffu, m, off));
    float ex = __expf(val - m);
    float s = ex;
#pragma unroll
    for (int off = 8; off >= 1; off >>= 1)
        s += __shfl_xor_sync(0xffffffffu, s, off);
    if (ok) out[(size_t)node0 * CLS + c] = val - m - __logf(s);
}

// ---------------- launch ----------------
extern "C" void kernel_launch(void* const* d_in, const int* in_sizes, int n_in,
                              void* d_out, int out_size) {
    const float* x     = (const float*)d_in[0];
    const void*  ei    = d_in[1];
    const float* W1    = (const float*)d_in[2];
    const float* attS1 = (const float*)d_in[3];
    const float* attD1 = (const float*)d_in[4];
    const float* bias1 = (const float*)d_in[5];
    const float* W2    = (const float*)d_in[6];
    const float* attS2 = (const float*)d_in[7];
    const float* attD2 = (const float*)d_in[8];
    const float* bias2 = (const float*)d_in[9];
    float* out = (float*)d_out;

    int n = in_sizes[0] / F_IN;      // 50000
    int E = in_sizes[1] / 2;         // 1600000

    void* p_deg = nullptr;
    cudaGetSymbolAddress(&p_deg, g_deg);
    cudaMemsetAsync(p_deg, 0, (size_t)n * sizeof(int));

    int GB = (n + 255) / 256;                 // gemm1 blocks (196)
    int CB = (E + 255) / 256;                 // count blocks (6250)
    int nb = (n + SCAN_B - 1) / SCAN_B;       // scan blocks (196)

    k_gemm1_count<<<GB + CB, 256>>>(x, W1, attS1, attD1, ei, n, E, GB); // kernel 1
    k_scan1<<<nb, SCAN_B>>>(n, nb);                                     // kernel 2
    k_scatter<<<(E + n + 255) / 256, 256>>>(ei, E, n);                  // kernel 3
    agg1 <<<(n + 7) / 8, 256>>>(bias1, n);                              // kernel 4 <- ncu lands here
    gemm2<<<(n + 15) / 16, 256>>>(W2, attS2, attD2, n);
    agg2 <<<(n + 15) / 16, 256>>>(bias2, out, n);
}

// round 13
// speedup vs baseline: 1.0704x; 1.0342x over previous
#include <cuda_runtime.h>
#include <cuda_fp16.h>
#include <cstdint>

#define MAXN 50000
#define MAXE 1600000
#define F_IN 512
#define C1 64      // heads*hid = 8*8
#define HEADS 8
#define CLS 16
#define SCAN_B 256

typedef unsigned long long ull;

// packed fp32x2 FMA (sm_103a)
#define FMA_F32X2(d, a, b, c) \
    asm("fma.rn.f32x2 %0, %1, %2, %3;" : "=l"(d) : "l"(a), "l"(b), "l"(c))
#define PACK_DUP_F32X2(d, f) \
    asm("mov.b64 %0, {%1, %1};" : "=l"(d) : "r"(__float_as_uint(f)))

// ---------------- scratch ----------------
__device__ __align__(16) int   g_deg[MAXN];        // zeroed via cudaMemsetAsync
__device__ __align__(16) int   g_tmp[MAXN];        // zeroed inside k_scan1
__device__ __align__(16) int   g_rowptr[MAXN + 1]; // block-local exclusive prefix
__device__ __align__(16) int   g_bsum[256];
__device__ __align__(16) int   g_boff[256];        // per-block offset
__device__            int      g_arrive = 0;       // last-block ticket (returns to 0 each call)
__device__ __align__(16) int   g_col[MAXE + MAXN + 8];   // +8 pad: unconditional int2 reads
__device__ __align__(16) float g_h1[(size_t)MAXN * C1];
__device__ __align__(16) float g_asrc1[MAXN * HEADS];
__device__ __align__(16) float g_adst1[MAXN * HEADS];
__device__ __align__(16) float g_h1act[(size_t)MAXN * C1];
__device__ __align__(16) float g_h2[(size_t)MAXN * CLS];
__device__ __align__(16) float g_asrc2[MAXN];
__device__ __align__(16) float g_adst2[MAXN];

// global rowptr = block-local prefix + per-block offset
__device__ __forceinline__ int rowp(int i) {
    return g_rowptr[i] + g_boff[i >> 8];
}

// Per-block int64-vs-int32 probe: deterministic for fixed input.
__device__ __forceinline__ bool block_detect_is64(const int* w32, long long e0, int E) {
    int hi = 0;
    long long e = e0 + threadIdx.x;
    if (e < E) hi = w32[2 * e + 1];
    return !__syncthreads_or(hi != 0);
}

__device__ __forceinline__ int load_edge(const void* ei, bool is64, size_t pos) {
    return is64 ? (int)((const long long*)ei)[pos] : ((const int*)ei)[pos];
}

// ================= fused GEMM1 (f32x2 packed) + edge count =================
#define TK 32
__global__ __launch_bounds__(256) void k_gemm1_count(
    const float* __restrict__ x, const float* __restrict__ W,
    const float* __restrict__ attS, const float* __restrict__ attD,
    const void* __restrict__ ei, int n, int E, int GB)
{
    if (blockIdx.x >= GB) {
        long long e0 = (long long)(blockIdx.x - GB) * 256;
        bool is64 = block_detect_is64((const int*)ei, e0, E);
        long long e = e0 + threadIdx.x;
        if (e < E) {
            int d = load_edge(ei, is64, (size_t)E + e);
            if ((unsigned)d < (unsigned)n) atomicAdd(&g_deg[d], 1);
        }
        return;
    }

    __shared__ __align__(16) float xs[TK][256 + 4];
    __shared__ __align__(16) float ws[TK][64 + 4];
    int tid = threadIdx.x;
    int tx = tid & 7;       // col group (== head)
    int ty = tid >> 3;      // row group 0..31
    int r0 = blockIdx.x * 256;

    ull acc2[8][4];
#pragma unroll
    for (int r = 0; r < 8; r++)
#pragma unroll
        for (int c = 0; c < 4; c++) acc2[r][c] = 0ull;

    for (int kc = 0; kc < F_IN; kc += TK) {
#pragma unroll
        for (int i = 0; i < 8; i++) {
            int idx = tid + 256 * i;
            int row = idx >> 3;
            int k4  = idx & 7;
            float4 v = make_float4(0.f, 0.f, 0.f, 0.f);
            int gr = r0 + row;
            if (gr < n) v = *(const float4*)&x[(size_t)gr * F_IN + kc + k4 * 4];
            xs[k4 * 4 + 0][row] = v.x;
            xs[k4 * 4 + 1][row] = v.y;
            xs[k4 * 4 + 2][row] = v.z;
            xs[k4 * 4 + 3][row] = v.w;
        }
#pragma unroll
        for (int i = 0; i < 2; i++) {
            int idx = tid + 256 * i;
            int k  = idx >> 4;
            int c4 = idx & 15;
            float4 v = *(const float4*)&W[(size_t)(kc + k) * C1 + c4 * 4];
            ws[k][c4 * 4 + 0] = v.x;
            ws[k][c4 * 4 + 1] = v.y;
            ws[k][c4 * 4 + 2] = v.z;
            ws[k][c4 * 4 + 3] = v.w;
        }
        __syncthreads();
#pragma unroll
        for (int k = 0; k < TK; k++) {
            float4 xa = *(const float4*)&xs[k][ty * 8];
            float4 xb = *(const float4*)&xs[k][ty * 8 + 4];
            ull wv2[4];
            {
                const ulonglong2* wp = (const ulonglong2*)&ws[k][tx * 8];
                ulonglong2 w01 = wp[0];
                ulonglong2 w23 = wp[1];
                wv2[0] = w01.x; wv2[1] = w01.y;
                wv2[2] = w23.x; wv2[3] = w23.y;
            }
            ull xp[8];
            PACK_DUP_F32X2(xp[0], xa.x); PACK_DUP_F32X2(xp[1], xa.y);
            PACK_DUP_F32X2(xp[2], xa.z); PACK_DUP_F32X2(xp[3], xa.w);
            PACK_DUP_F32X2(xp[4], xb.x); PACK_DUP_F32X2(xp[5], xb.y);
            PACK_DUP_F32X2(xp[6], xb.z); PACK_DUP_F32X2(xp[7], xb.w);
#pragma unroll
            for (int r = 0; r < 8; r++)
#pragma unroll
                for (int c = 0; c < 4; c++)
                    FMA_F32X2(acc2[r][c], xp[r], wv2[c], acc2[r][c]);
        }
        __syncthreads();
    }

    float as[8], ad[8];
#pragma unroll
    for (int c = 0; c < 8; c++) { as[c] = attS[tx * 8 + c]; ad[c] = attD[tx * 8 + c]; }
#pragma unroll
    for (int r = 0; r < 8; r++) {
        int gr = r0 + ty * 8 + r;
        if (gr < n) {
            float a[8];
#pragma unroll
            for (int c = 0; c < 4; c++) {
                uint2 u = *(uint2*)&acc2[r][c];
                a[2 * c]     = __uint_as_float(u.x);
                a[2 * c + 1] = __uint_as_float(u.y);
            }
            float s = 0.f, d = 0.f;
#pragma unroll
            for (int c = 0; c < 8; c++) {
                s = fmaf(a[c], as[c], s);
                d = fmaf(a[c], ad[c], d);
            }
            float4 v0 = make_float4(a[0], a[1], a[2], a[3]);
            float4 v1 = make_float4(a[4], a[5], a[6], a[7]);
            *(float4*)&g_h1[(size_t)gr * C1 + tx * 8]     = v0;
            *(float4*)&g_h1[(size_t)gr * C1 + tx * 8 + 4] = v1;
            g_asrc1[gr * HEADS + tx] = s;
            g_adst1[gr * HEADS + tx] = d;
        }
    }
}

// ================= single-pass block scan (last block folds scan2) =================
__device__ __forceinline__ int warp_incl_scan(int x) {
#pragma unroll
    for (int o = 1; o < 32; o <<= 1) {
        int t = __shfl_up_sync(0xffffffffu, x, o);
        if ((threadIdx.x & 31) >= o) x += t;
    }
    return x;
}

__global__ void k_scan1(int n, int nb) {
    __shared__ int wsum[8];
    __shared__ int is_last;
    int i = blockIdx.x * SCAN_B + threadIdx.x;
    int lane = threadIdx.x & 31, wid = threadIdx.x >> 5;
    if (i < n) g_tmp[i] = 0;                // replaces the g_tmp memset
    int v = (i < n) ? g_deg[i] + 1 : 0;     // +1 = self-loop
    int x = warp_incl_scan(v);
    if (lane == 31) wsum[wid] = x;
    __syncthreads();
    if (wid == 0) {
        int y = (lane < 8) ? wsum[lane] : 0;
#pragma unroll
        for (int o = 1; o < 8; o <<= 1) {
            int t = __shfl_up_sync(0xffffffffu, y, o);
            if (lane >= o) y += t;
        }
        if (lane < 8) wsum[lane] = y;
    }
    __syncthreads();
    int excl = x - v + (wid > 0 ? wsum[wid - 1] : 0);
    if (i <= n) g_rowptr[i] = excl;
    if (threadIdx.x == 0) g_bsum[blockIdx.x] = wsum[7];

    __threadfence();
    if (threadIdx.x == 0) {
        int t = atomicAdd(&g_arrive, 1);
        is_last = (t == gridDim.x - 1);
    }
    __syncthreads();
    if (is_last) {
        int tt = threadIdx.x;
        int vv = (tt < nb) ? g_bsum[tt] : 0;
        int xx = warp_incl_scan(vv);
        if (lane == 31) wsum[wid] = xx;
        __syncthreads();
        if (wid == 0) {
            int y = (lane < 8) ? wsum[lane] : 0;
#pragma unroll
            for (int o = 1; o < 8; o <<= 1) {
                int t2 = __shfl_up_sync(0xffffffffu, y, o);
                if (lane >= o) y += t2;
            }
            if (lane < 8) wsum[lane] = y;
        }
        __syncthreads();
        int ex2 = xx - vv + (wid > 0 ? wsum[wid - 1] : 0);
        if (tt < nb) g_boff[tt] = ex2;
        if (tt == 0) g_arrive = 0;          // reset for next graph replay
    }
}

// ================= scatter (edges then self-loops) =================
__global__ void k_scatter(const void* __restrict__ ei, int E, int n) {
    long long e0 = (long long)blockIdx.x * 256;
    bool is64 = block_detect_is64((const int*)ei, e0, E);
    long long i = e0 + threadIdx.x;
    int s, d;
    if (i < E) {
        d = load_edge(ei, is64, (size_t)E + i);
        if ((unsigned)d >= (unsigned)n) return;       // must match count guard
        s = load_edge(ei, is64, (size_t)i);
        if ((unsigned)s >= (unsigned)n) s = 0;
    } else if (i < E + n) {
        s = d = (int)(i - E);
    } else return;
    int pos = rowp(d) + atomicAdd(&g_tmp[d], 1);
    g_col[pos] = s;
}

// ================= layer-1 edge softmax + aggregate + bias + elu =================
// 2 dst nodes per warp (half-warp each). Within a half (hl = lane&15):
//   feature lanes: hl owns channels 4hl..4hl+3 (head hown = hl>>1), float4/f32x2
//   exp lanes:     (j = hl>>3, h = hl&7) -> one exp per lane per 2 edges
// Branch-free divergence: loop to max(itersA, itersB); invalid edges get w=0.
__global__ __launch_bounds__(256) void agg1(const float* __restrict__ bias1, int n) {
    int gwarp = (blockIdx.x * blockDim.x + threadIdx.x) >> 5;
    int lane  = threadIdx.x & 31;
    int half  = lane >> 4;
    int hl    = lane & 15;
    int half0 = half << 4;
    int nd = gwarp * 2 + half;
    bool okn = nd < n;
    int ndc = okn ? nd : 0;
    int h    = hl & 7;        // head this lane exponentiates
    int j    = hl >> 3;       // edge slot (0/1) this lane exponentiates
    int hown = hl >> 1;       // head owning channels 4hl..4hl+3

    float adv = g_adst1[ndc * HEADS + h];
    int beg = rowp(ndc);
    int end = okn ? rowp(ndc + 1) : beg;

    ull acc01 = 0ull, acc23 = 0ull;
    float den = 0.f;

    // prologue (straight-line, no divergence): handle odd beg edge if present
    bool pro = (beg & 1) && (beg < end);
    {
        int s0 = g_col[beg];                       // always a valid index
        float a = g_asrc1[s0 * HEADS + h] + adv;
        a = a > 0.f ? a : 0.2f * a;
        float w = __expf(a);
        float wg = pro ? w : 0.f;
        den += (j == 0) ? wg : 0.f;
        float w0o = __shfl_sync(0xffffffffu, wg, half0 + hown);
        ulonglong2 u0 = *(const ulonglong2*)&g_h1[(size_t)s0 * C1 + 4 * hl];
        ull wp0; PACK_DUP_F32X2(wp0, w0o);
        FMA_F32X2(acc01, wp0, u0.x, acc01);
        FMA_F32X2(acc23, wp0, u0.y, acc23);
    }
    int e0 = beg + (beg & 1);                      // 2-aligned start of main loop
    int iters = end - e0 + 1; iters = iters < 0 ? 0 : (iters >> 1);
    int oth = __shfl_xor_sync(0xffffffffu, iters, 16);
    int mx = iters > oth ? iters : oth;

    for (int k = 0; k < mx; k++) {
        int ec = e0 + 2 * k;                       // even; int2 read is 8B-aligned, array padded
        int2 c2 = *(const int2*)&g_col[ec];
        bool v0 = ec < end, v1 = ec + 1 < end;
        int s0 = v0 ? c2.x : 0;
        int s1 = v1 ? c2.y : 0;
        int sj = j ? s1 : s0;
        float a = g_asrc1[sj * HEADS + h] + adv;
        ulonglong2 u0 = *(const ulonglong2*)&g_h1[(size_t)s0 * C1 + 4 * hl];
        ulonglong2 u1 = *(const ulonglong2*)&g_h1[(size_t)s1 * C1 + 4 * hl];
        a = a > 0.f ? a : 0.2f * a;                // leaky_relu
        float w = __expf(a);
        bool vj = j ? v1 : v0;
        w = vj ? w : 0.f;
        den += w;
        float w0o = __shfl_sync(0xffffffffu, w, half0 + hown);
        float w1o = __shfl_sync(0xffffffffu, w, half0 + 8 + hown);
        ull wp0, wp1;
        PACK_DUP_F32X2(wp0, w0o);
        PACK_DUP_F32X2(wp1, w1o);
        FMA_F32X2(acc01, wp0, u0.x, acc01);
        FMA_F32X2(acc23, wp0, u0.y, acc23);
        FMA_F32X2(acc01, wp1, u1.x, acc01);
        FMA_F32X2(acc23, wp1, u1.y, acc23);
    }

    // fold den over j groups within the half (lanes hl and hl^8 share head h)
    den += __shfl_xor_sync(0xffffffffu, den, 8);
    float deno = __shfl_sync(0xffffffffu, den, half0 + hown);  // lane half0+hown has h==hown

    if (okn) {
        uint2 ua = *(uint2*)&acc01;
        uint2 ub = *(uint2*)&acc23;
        float4 bv = *(const float4*)&bias1[4 * hl];
        float o0 = __uint_as_float(ua.x) / deno + bv.x;
        float o1 = __uint_as_float(ua.y) / deno + bv.y;
        float o2 = __uint_as_float(ub.x) / deno + bv.z;
        float o3 = __uint_as_float(ub.y) / deno + bv.w;
        o0 = o0 > 0.f ? o0 : expm1f(o0);           // elu
        o1 = o1 > 0.f ? o1 : expm1f(o1);
        o2 = o2 > 0.f ? o2 : expm1f(o2);
        o3 = o3 > 0.f ? o3 : expm1f(o3);
        *(float4*)&g_h1act[(size_t)nd * C1 + 4 * hl] = make_float4(o0, o1, o2, o3);
    }
}

// ================= GEMM2: h2 = h1act @ W2, fused scalar logits =================
__global__ __launch_bounds__(256) void gemm2(
    const float* __restrict__ W2, const float* __restrict__ aS,
    const float* __restrict__ aD, int n)
{
    __shared__ float ws[64 * 16];
    int tid = threadIdx.x;
    for (int i = tid; i < 64 * 16; i += 256) ws[i] = W2[i];
    __syncthreads();

    int warp = tid >> 5, lane = tid & 31;
    int row0 = (blockIdx.x * 8 + warp) * 2 + (lane >> 4);
    int c = lane & 15;
    bool ok = row0 < n;
    int row = ok ? row0 : 0;

    float xr[4];
#pragma unroll
    for (int j = 0; j < 4; j++) xr[j] = g_h1act[(size_t)row * C1 + c + 16 * j];

    float acc = 0.f;
#pragma unroll
    for (int k = 0; k < 64; k++) {
        float xk = __shfl_sync(0xffffffffu, xr[k >> 4], (lane & 16) | (k & 15));
        acc = fmaf(xk, ws[k * 16 + c], acc);
    }

    float ts = acc * aS[c];
    float td = acc * aD[c];
#pragma unroll
    for (int off = 8; off >= 1; off >>= 1) {
        ts += __shfl_xor_sync(0xffffffffu, ts, off);
        td += __shfl_xor_sync(0xffffffffu, td, off);
    }
    if (ok) {
        g_h2[(size_t)row * CLS + c] = acc;
        if (c == 0) { g_asrc2[row] = ts; g_adst2[row] = td; }
    }
}

// ================= layer-2 aggregate + bias + log_softmax =================
__global__ __launch_bounds__(256) void agg2(
    const float* __restrict__ bias2, float* __restrict__ out, int n)
{
    int warp = (blockIdx.x * blockDim.x + threadIdx.x) >> 5;
    int lane = threadIdx.x & 31;
    int node0 = warp * 2 + (lane >> 4);
    int c = lane & 15;
    bool ok = node0 < n;
    int nd = ok ? node0 : 0;

    float adv = g_adst2[nd];
    int beg = rowp(nd);
    int end = ok ? rowp(nd + 1) : beg;
    float acc = 0.f, den = 0.f;
    int e = beg;
    for (; e + 2 <= end; e += 2) {
        int s0 = g_col[e], s1 = g_col[e + 1];
        float a0 = g_asrc2[s0] + adv;
        float a1 = g_asrc2[s1] + adv;
        float f0 = g_h2[(size_t)s0 * CLS + c];
        float f1 = g_h2[(size_t)s1 * CLS + c];
        a0 = a0 > 0.f ? a0 : 0.2f * a0;
        a1 = a1 > 0.f ? a1 : 0.2f * a1;
        float w0 = __expf(a0), w1 = __expf(a1);
        den += w0 + w1;
        acc = fmaf(w0, f0, acc);
        acc = fmaf(w1, f1, acc);
    }
    if (e < end) {
        int s0 = g_col[e];
        float a0 = g_asrc2[s0] + adv;
        a0 = a0 > 0.f ? a0 : 0.2f * a0;
        float w0 = __expf(a0);
        den += w0;
        acc = fmaf(w0, g_h2[(size_t)s0 * CLS + c], acc);
    }
    float val = ok ? (acc / den + bias2[c]) : 0.f;
    float m = val;
#pragma unroll
    for (int off = 8; off >= 1; off >>= 1)
        m = fmaxf(m, __shfl_xor_sync(0xffffffffu, m, off));
    float ex = __expf(val - m);
    float s = ex;
#pragma unroll
    for (int off = 8; off >= 1; off >>= 1)
        s += __shfl_xor_sync(0xffffffffu, s, off);
    if (ok) out[(size_t)node0 * CLS + c] = val - m - __logf(s);
}

// ---------------- launch ----------------
extern "C" void kernel_launch(void* const* d_in, const int* in_sizes, int n_in,
                              void* d_out, int out_size) {
    const float* x     = (const float*)d_in[0];
    const void*  ei    = d_in[1];
    const float* W1    = (const float*)d_in[2];
    const float* attS1 = (const float*)d_in[3];
    const float* attD1 = (const float*)d_in[4];
    const float* bias1 = (const float*)d_in[5];
    const float* W2    = (const float*)d_in[6];
    const float* attS2 = (const float*)d_in[7];
    const float* attD2 = (const float*)d_in[8];
    const float* bias2 = (const float*)d_in[9];
    float* out = (float*)d_out;

    int n = in_sizes[0] / F_IN;      // 50000
    int E = in_sizes[1] / 2;         // 1600000

    void* p_deg = nullptr;
    cudaGetSymbolAddress(&p_deg, g_deg);
    cudaMemsetAsync(p_deg, 0, (size_t)n * sizeof(int));

    int GB = (n + 255) / 256;                 // gemm1 blocks (196)
    int CB = (E + 255) / 256;                 // count blocks (6250)
    int nb = (n + SCAN_B - 1) / SCAN_B;       // scan blocks (196)
    int AW = (n + 1) / 2;                     // agg1 warps (2 nodes each)

    k_gemm1_count<<<GB + CB, 256>>>(x, W1, attS1, attD1, ei, n, E, GB); // kernel 1
    k_scan1<<<nb, SCAN_B>>>(n, nb);                                     // kernel 2
    k_scatter<<<(E + n + 255) / 256, 256>>>(ei, E, n);                  // kernel 3
    agg1 <<<(AW + 7) / 8, 256>>>(bias1, n);                             // kernel 4 <- ncu lands here
    gemm2<<<(n + 15) / 16, 256>>>(W2, attS2, attD2, n);
    agg2 <<<(n + 15) / 16, 256>>>(bias2, out, n);
}